// round 3
// baseline (speedup 1.0000x reference)
#include <cuda_runtime.h>
#include <math.h>

#define NB    15
#define C     50
#define TILE  128
#define NBLOCKS 1184   // 148 SMs * 8; rows/block <= 1792 < 2^11 (packing bound)

// Global scratch (allocation-free): per-bin totals.
__device__ unsigned long long g_cnt[NB];
__device__ unsigned long long g_acc[NB];
__device__ double             g_conf[NB];

__global__ void ece_zero_kernel() {
    int i = threadIdx.x;
    if (i < NB) { g_cnt[i] = 0ULL; g_acc[i] = 0ULL; g_conf[i] = 0.0; }
}

__global__ void __launch_bounds__(TILE)
ece_main_kernel(const float* __restrict__ logits,
                const int* __restrict__ labels,   // JAX x64-disabled: int64 request -> int32 buffer
                int n)
{
    __shared__ float s_tile[TILE * C];               // 25600 B
    __shared__ unsigned long long s_bins[NB];

    const int tid = threadIdx.x;
    if (tid < NB) s_bins[tid] = 0ULL;

    const int ntiles = (n + TILE - 1) / TILE;

    for (int t = blockIdx.x; t < ntiles; t += gridDim.x) {
        __syncthreads();   // WAR: previous tile's compute done before overwrite; also orders s_bins init

        // ---- coalesced GMEM -> SMEM copy of TILE rows ----
        const int rows_here = min(TILE, n - t * TILE);
        const int nfloat = rows_here * C;
        const float* gsrc = logits + (size_t)t * TILE * C;
        {
            const int n4 = nfloat >> 2;              // float4 count (tile base is 16B aligned)
            const float4* src4 = (const float4*)gsrc;
            float4* dst4 = (float4*)s_tile;
            for (int i = tid; i < n4; i += TILE) dst4[i] = src4[i];
            for (int i = (n4 << 2) + tid; i < nfloat; i += TILE) s_tile[i] = gsrc[i];
        }
        __syncthreads();

        // ---- thread-per-row compute ----
        const int row = t * TILE + tid;
        if (row < n) {
            float vals[C];
            const float2* p = (const float2*)(s_tile + tid * C);  // byte off tid*200, 8B aligned
            #pragma unroll
            for (int i = 0; i < C / 2; i++) {
                float2 v = p[i];
                vals[2 * i]     = v.x;
                vals[2 * i + 1] = v.y;
            }

            // argmax / max (first occurrence on ties, matching jnp.argmax)
            float m = vals[0];
            int arg = 0;
            #pragma unroll
            for (int i = 1; i < C; i++) {
                if (vals[i] > m) { m = vals[i]; arg = i; }
            }

            // confidence = max softmax prob = 1 / sum exp(l - m)
            float s = 0.0f;
            #pragma unroll
            for (int i = 0; i < C; i++) s += __expf(vals[i] - m);
            float conf = 1.0f / s;

            int acc = (arg == labels[row]) ? 1 : 0;

            // bin = clip(searchsorted_left(uppers, conf), 0, 14); uppers[i]=(i+1)/15
            int bin = (int)ceilf(conf * 15.0f) - 1;
            bin = bin < 0 ? 0 : (bin > NB - 1 ? NB - 1 : bin);

            // one packed 64-bit shared atomic per row:
            //   bits [0,42):  conf in 2^-30 fixed point  (<= 1792 * 2^30 < 2^41)
            //   bits [42,53): acc sum                    (<= 1792 < 2^11)
            //   bits [53,64): count                      (<= 1792 < 2^11)
            unsigned long long cf = (unsigned long long)(conf * 1073741824.0f + 0.5f);
            unsigned long long pack = cf | ((unsigned long long)acc << 42) | (1ULL << 53);
            atomicAdd(&s_bins[bin], pack);
        }
    }

    __syncthreads();
    if (tid < NB) {
        unsigned long long v = s_bins[tid];
        if (v) {
            unsigned long long cf = v & ((1ULL << 42) - 1);
            unsigned long long ac = (v >> 42) & 0x7FFULL;
            unsigned long long ct = v >> 53;
            atomicAdd(&g_cnt[tid], ct);
            atomicAdd(&g_acc[tid], ac);
            atomicAdd(&g_conf[tid], (double)cf * (1.0 / 1073741824.0));
        }
    }
}

__global__ void ece_final_kernel(float* __restrict__ out, int n)
{
    // out layout: [0] ece, [1..15] bin_over_confidence, [16..30] prop_in_bin
    double ece = 0.0;
    for (int i = 0; i < NB; i++) {
        double ct = (double)g_cnt[i];
        double prop = ct / (double)n;
        bool nonempty = ct > 0.0;
        double denom = nonempty ? ct : 1.0;
        double avg_acc  = (double)g_acc[i] / denom;
        double avg_conf = g_conf[i] / denom;
        double gap = avg_conf - avg_acc;
        out[1 + i]  = (float)(nonempty ? gap * prop : 0.0);
        out[16 + i] = (float)prop;
        if (nonempty) ece += fabs(gap) * prop;
    }
    out[0] = (float)ece;
}

extern "C" void kernel_launch(void* const* d_in, const int* in_sizes, int n_in,
                              void* d_out, int out_size)
{
    const float* logits = (const float*)d_in[0];
    const int*   labels = (const int*)d_in[1];
    int n = in_sizes[1];   // label count = number of rows

    ece_zero_kernel<<<1, 32>>>();
    ece_main_kernel<<<NBLOCKS, TILE>>>(logits, labels, n);
    ece_final_kernel<<<1, 1>>>((float*)d_out, n);
}